// round 1
// baseline (speedup 1.0000x reference)
#include <cuda_runtime.h>

// CorrelationNetwork: out[b,pi,pj,h,w] = leaky_relu( (1/32) * sum_c x1[b,c,h,w] *
//                     x2_pad[b,c, h+2*pi-20, w+2*pj-20], 0.1 )
// B=4, C=32, H=32, W=1024, PATCH=21, DIL=2, PAD=20.

#define WT     128     // w-tile per block
#define SLICE  176     // padded floats per x2 slice row (need 168 = WT+40)
#define NWARP  8
#define PATCH  21

__device__ __forceinline__ unsigned long long ffma2(unsigned long long a,
                                                    unsigned long long b,
                                                    unsigned long long c) {
    unsigned long long d;
    asm("fma.rn.f32x2 %0, %1, %2, %3;" : "=l"(d) : "l"(a), "l"(b), "l"(c));
    return d;
}

extern __shared__ float smem[];

__global__ void __launch_bounds__(256, 1)
corr_kernel(const float* __restrict__ x1, const float* __restrict__ x2,
            float* __restrict__ out)
{
    const int w0   = blockIdx.x * WT;
    const int h    = blockIdx.y;
    const int b    = blockIdx.z;
    const int tid  = threadIdx.x;
    const int wid  = tid >> 5;
    const int lane = tid & 31;

    float* x1s = smem;                                   // [32][WT]
    float* x2s = smem + 32 * WT + wid * 32 * SLICE;      // per-warp [32][SLICE]

    // ---- stage x1 tile: 32 channels x WT floats (float4 loads) ----
    {
        const int nf4 = 32 * (WT / 4);                   // 1024 float4s
        for (int f = tid; f < nf4; f += 256) {
            const int c = f >> 5;                        // WT/4 == 32
            const int j = f & 31;
            const float4 v = *reinterpret_cast<const float4*>(
                x1 + ((size_t)(b * 32 + c) * 32 + h) * 1024 + w0 + 4 * j);
            reinterpret_cast<float4*>(x1s)[f] = v;
        }
    }
    __syncthreads();

    // warp `wid` handles pi = wid, wid+8, wid+16
    for (int pi = wid; pi < PATCH; pi += NWARP) {
        const int h2 = h + 2 * pi - 20;

        // ---- load per-warp x2 slice: lane == channel, w in [w0-20, w0+147] ----
        {
            float* dst = x2s + lane * SLICE;
            if (h2 >= 0 && h2 < 32) {
                const float* src = x2 + ((size_t)(b * 32 + lane) * 32 + h2) * 1024;
                const int wb = w0 - 20;
                #pragma unroll 6
                for (int j = 0; j < 42; j++) {
                    const int w2 = wb + 4 * j;
                    float4 v;
                    if (w2 >= 0 && w2 <= 1020) {
                        v = *reinterpret_cast<const float4*>(src + w2);
                    } else {
                        v.x = (w2     >= 0 && w2     < 1024) ? src[w2]     : 0.f;
                        v.y = (w2 + 1 >= 0 && w2 + 1 < 1024) ? src[w2 + 1] : 0.f;
                        v.z = (w2 + 2 >= 0 && w2 + 2 < 1024) ? src[w2 + 2] : 0.f;
                        v.w = (w2 + 3 >= 0 && w2 + 3 < 1024) ? src[w2 + 3] : 0.f;
                    }
                    *reinterpret_cast<float4*>(dst + 4 * j) = v;
                }
            } else {
                const float4 z = make_float4(0.f, 0.f, 0.f, 0.f);
                #pragma unroll
                for (int j = 0; j < 42; j++)
                    *reinterpret_cast<float4*>(dst + 4 * j) = z;
            }
        }
        __syncwarp();

        // ---- accumulate: 4 w's (2 f32x2 pairs) x 21 pj per thread ----
        unsigned long long acc0[PATCH], acc1[PATCH];
        #pragma unroll
        for (int p = 0; p < PATCH; p++) { acc0[p] = 0ull; acc1[p] = 0ull; }

        const float* x1r = x1s + 4 * lane;
        const float* x2r = x2s + 4 * lane;

        #pragma unroll 2
        for (int c = 0; c < 32; c++) {
            const ulonglong2 a =
                *reinterpret_cast<const ulonglong2*>(x1r + c * WT);
            #pragma unroll
            for (int q = 0; q < 11; q++) {
                // x2 pairs at even offsets tile the 44-float window exactly:
                // pair index k feeds acc0[k] (w pair 0) and acc1[k-1] (w pair 1)
                const ulonglong2 pq =
                    *reinterpret_cast<const ulonglong2*>(x2r + c * SLICE + 4 * q);
                {
                    constexpr_dummy: ;
                }
                const int k0 = 2 * q;
                if (k0 < PATCH) acc0[k0]     = ffma2(a.x, pq.x, acc0[k0]);
                if (k0 >= 1)    acc1[k0 - 1] = ffma2(a.y, pq.x, acc1[k0 - 1]);
                const int k1 = 2 * q + 1;
                if (k1 < PATCH) acc0[k1]     = ffma2(a.x, pq.y, acc0[k1]);
                                acc1[k1 - 1] = ffma2(a.y, pq.y, acc1[k1 - 1]);
            }
        }

        // ---- epilogue: normalize by C=32, leaky_relu(0.1), store ----
        const float sp = 0.03125f;    // 1/32
        const float sn = 0.003125f;   // 0.1/32
        #pragma unroll
        for (int p = 0; p < PATCH; p++) {
            float* op = out + (((size_t)b * 441 + pi * 21 + p) * 32 + h) * 1024
                            + w0 + 4 * lane;
            float2 v0 = *reinterpret_cast<float2*>(&acc0[p]);
            float2 v1 = *reinterpret_cast<float2*>(&acc1[p]);
            v0.x *= (v0.x < 0.f) ? sn : sp;
            v0.y *= (v0.y < 0.f) ? sn : sp;
            v1.x *= (v1.x < 0.f) ? sn : sp;
            v1.y *= (v1.y < 0.f) ? sn : sp;
            *reinterpret_cast<float2*>(op)     = v0;   // w = w0+4*lane+{0,1}
            *reinterpret_cast<float2*>(op + 2) = v1;   // w = w0+4*lane+{2,3}
        }

        __syncwarp();   // slice reads done before next pi overwrites it
    }
}

extern "C" void kernel_launch(void* const* d_in, const int* in_sizes, int n_in,
                              void* d_out, int out_size) {
    const float* x1 = (const float*)d_in[0];
    const float* x2 = (const float*)d_in[1];
    float* out = (float*)d_out;

    const size_t smem_bytes = (size_t)(32 * WT + NWARP * 32 * SLICE) * sizeof(float); // 192 KB
    cudaFuncSetAttribute(corr_kernel,
                         cudaFuncAttributeMaxDynamicSharedMemorySize,
                         (int)smem_bytes);

    dim3 grid(1024 / WT, 32, 4);   // (w-tiles, H, B)
    corr_kernel<<<grid, 256, smem_bytes>>>(x1, x2, out);
}

// round 2
// speedup vs baseline: 1.6939x; 1.6939x over previous
#include <cuda_runtime.h>

// out[b,pi,pj,h,w] = leaky_relu( (1/32) * sum_c x1[b,c,h,w] *
//                    x2_pad[b,c, h+2*pi-20, w+2*pj-20], 0.1 )
// B=4, C=32, H=32, W=1024, PATCH=21, DIL=2, PAD=20.

#define WT     128     // w-tile per block
#define SLICE  172     // slice row stride in floats (need 168; 172 -> 12-bank lane shift, conflict-free STS)
#define PATCH  21

__device__ __forceinline__ unsigned long long ffma2(unsigned long long a,
                                                    unsigned long long b,
                                                    unsigned long long c) {
    unsigned long long d;
    asm("fma.rn.f32x2 %0, %1, %2, %3;" : "=l"(d) : "l"(a), "l"(b), "l"(c));
    return d;
}

extern __shared__ float smem[];

__global__ void __launch_bounds__(128, 2)
corr_kernel(const float* __restrict__ x1, const float* __restrict__ x2,
            float* __restrict__ out)
{
    const int w0   = blockIdx.x * WT;
    const int h    = blockIdx.y;
    const int b    = blockIdx.z;
    const int tid  = threadIdx.x;
    const int wid  = tid >> 5;          // 4 warps
    const int lane = tid & 31;
    const int g    = lane >> 1;         // w-group: 16 groups of 8 w's
    const int half = lane & 1;          // 0: pj 0..10, 1: pj 10..20

    float* x1s = smem;                                   // [32][WT]
    float* x2s = smem + 32 * WT + wid * 32 * SLICE;      // per-warp [32][SLICE]

    // ---- stage x1 tile: 32 channels x WT floats ----
    for (int f = tid; f < 32 * (WT / 4); f += 128) {
        const int c = f >> 5;
        const int j = f & 31;
        reinterpret_cast<float4*>(x1s)[f] = *reinterpret_cast<const float4*>(
            x1 + ((size_t)(b * 32 + c) * 32 + h) * 1024 + w0 + 4 * j);
    }
    __syncthreads();

    // warp `wid` handles pi = wid, wid+4, ...
    for (int pi = wid; pi < PATCH; pi += 4) {
        const int h2 = h + 2 * pi - 20;

        // ---- load per-warp x2 slice: lane == channel, w in [w0-20, w0+147] ----
        {
            float* dst = x2s + lane * SLICE;
            if (h2 >= 0 && h2 < 32) {
                const float* src = x2 + ((size_t)(b * 32 + lane) * 32 + h2) * 1024;
                const int wb = w0 - 20;
                #pragma unroll 6
                for (int j = 0; j < 42; j++) {
                    const int w2 = wb + 4 * j;
                    float4 v;
                    if (w2 >= 0 && w2 <= 1020) {
                        v = *reinterpret_cast<const float4*>(src + w2);
                    } else {
                        v.x = (w2     >= 0 && w2     < 1024) ? src[w2]     : 0.f;
                        v.y = (w2 + 1 >= 0 && w2 + 1 < 1024) ? src[w2 + 1] : 0.f;
                        v.z = (w2 + 2 >= 0 && w2 + 2 < 1024) ? src[w2 + 2] : 0.f;
                        v.w = (w2 + 3 >= 0 && w2 + 3 < 1024) ? src[w2 + 3] : 0.f;
                    }
                    *reinterpret_cast<float4*>(dst + 4 * j) = v;
                }
            } else {
                const float4 z = make_float4(0.f, 0.f, 0.f, 0.f);
                #pragma unroll
                for (int j = 0; j < 42; j++)
                    *reinterpret_cast<float4*>(dst + 4 * j) = z;
            }
        }
        __syncwarp();

        // ---- accumulate: 8 w's (4 f32x2 pairs) x 11 pj per thread ----
        // acc[p][q]: output pj index (pj = p + 10*half), w-pair q of this lane's
        // 8 w's. Inner relation: acc[p][q] += a[q] (x) P[p+q], where P[k] is the
        // f32x2 pair at even float offset 2k in this lane's 28-float window.
        unsigned long long acc[11][4];
        #pragma unroll
        for (int p = 0; p < 11; p++)
            #pragma unroll
            for (int q = 0; q < 4; q++) acc[p][q] = 0ull;

        const float* x1p = x1s + 8 * g;
        const float* xwp = x2s + 8 * g + 20 * half;   // 20 floats = 80B, 16B aligned

        #pragma unroll 2
        for (int c = 0; c < 32; c++) {
            const ulonglong2 A0 =
                *reinterpret_cast<const ulonglong2*>(x1p + c * WT);
            const ulonglong2 A1 =
                *reinterpret_cast<const ulonglong2*>(x1p + c * WT + 4);
            const unsigned long long a[4] = {A0.x, A0.y, A1.x, A1.y};

            ulonglong2 X[7];
            const float* bp = xwp + c * SLICE;
            #pragma unroll
            for (int j = 0; j < 7; j++)
                X[j] = *reinterpret_cast<const ulonglong2*>(bp + 4 * j);

            #pragma unroll
            for (int p = 0; p < 11; p++) {
                #pragma unroll
                for (int q = 0; q < 4; q++) {
                    const int k = p + q;                       // 0..13
                    const unsigned long long pk = (k & 1) ? X[k >> 1].y
                                                          : X[k >> 1].x;
                    acc[p][q] = ffma2(a[q], pk, acc[p][q]);
                }
            }
        }

        // ---- epilogue: /32, leaky_relu(0.1), store 8 floats per p ----
        const float sp = 0.03125f;    // 1/32
        const float sn = 0.003125f;   // 0.1/32
        #pragma unroll
        for (int p = 0; p < 11; p++) {
            if (half == 1 && p == 0) continue;     // pj=10 duplicated by half A
            const int pj = half ? (p + 10) : p;
            float* op = out + (((size_t)b * 441 + pi * 21 + pj) * 32 + h) * 1024
                            + w0 + 8 * g;
            float v[8];
            #pragma unroll
            for (int q = 0; q < 4; q++) {
                float2 f = *reinterpret_cast<float2*>(&acc[p][q]);
                v[2 * q]     = f.x * ((f.x < 0.f) ? sn : sp);
                v[2 * q + 1] = f.y * ((f.y < 0.f) ? sn : sp);
            }
            *reinterpret_cast<float4*>(op)     = make_float4(v[0], v[1], v[2], v[3]);
            *reinterpret_cast<float4*>(op + 4) = make_float4(v[4], v[5], v[6], v[7]);
        }

        __syncwarp();   // slice reads done before next pi overwrites it
    }
}

extern "C" void kernel_launch(void* const* d_in, const int* in_sizes, int n_in,
                              void* d_out, int out_size) {
    const float* x1 = (const float*)d_in[0];
    const float* x2 = (const float*)d_in[1];
    float* out = (float*)d_out;

    const size_t smem_bytes =
        (size_t)(32 * WT + 4 * 32 * SLICE) * sizeof(float);   // 104448 B
    cudaFuncSetAttribute(corr_kernel,
                         cudaFuncAttributeMaxDynamicSharedMemorySize,
                         (int)smem_bytes);

    dim3 grid(1024 / WT, 32, 4);   // (w-tiles, H, B)
    corr_kernel<<<grid, 128, smem_bytes>>>(x1, x2, out);
}